// round 1
// baseline (speedup 1.0000x reference)
#include <cuda_runtime.h>
#include <math.h>

// Problem constants
#define NTOK 8192
#define NEXP 64

// Scratch (device globals: allocation-free)
__device__ float g_h[NTOK * 4096];     // up output after GELU (128 MB)
__device__ int   g_idx_up[NTOK * 2];
__device__ float g_prob_up[NTOK * 2];
__device__ int   g_idx_dn[NTOK * 2];
__device__ float g_prob_dn[NTOK * 2];

// ---------------------------------------------------------------------------
// Router: logits = x @ W^T  (W: [64, D]) fused with top-2 + softmax.
// Block handles 64 tokens x 64 experts. 256 threads, 4x4 micro-tile.
// ---------------------------------------------------------------------------
template <int D>
__global__ void __launch_bounds__(256, 2)
router_kernel(const float* __restrict__ x, const float* __restrict__ W,
              int* __restrict__ idx, float* __restrict__ prob)
{
    __shared__ float xs[64][33];
    __shared__ float ws[64][33];
    __shared__ float ls[64][65];

    const int tid   = threadIdx.x;
    const int tok0  = blockIdx.x * 64;
    const int trow0 = (tid >> 4) * 4;   // token sub-tile
    const int ecol0 = (tid & 15) * 4;   // expert sub-tile

    float acc[4][4];
#pragma unroll
    for (int i = 0; i < 4; i++)
#pragma unroll
        for (int j = 0; j < 4; j++) acc[i][j] = 0.f;

    for (int d0 = 0; d0 < D; d0 += 32) {
#pragma unroll
        for (int l = tid; l < 2048; l += 256) {
            int r = l >> 5, c = l & 31;
            xs[r][c] = x[(tok0 + r) * D + d0 + c];
            ws[r][c] = W[r * D + d0 + c];
        }
        __syncthreads();
#pragma unroll
        for (int dd = 0; dd < 32; dd++) {
            float av[4], bv[4];
#pragma unroll
            for (int i = 0; i < 4; i++) av[i] = xs[trow0 + i][dd];
#pragma unroll
            for (int j = 0; j < 4; j++) bv[j] = ws[ecol0 + j][dd];
#pragma unroll
            for (int i = 0; i < 4; i++)
#pragma unroll
                for (int j = 0; j < 4; j++) acc[i][j] += av[i] * bv[j];
        }
        __syncthreads();
    }

#pragma unroll
    for (int i = 0; i < 4; i++)
#pragma unroll
        for (int j = 0; j < 4; j++) ls[trow0 + i][ecol0 + j] = acc[i][j];
    __syncthreads();

    if (tid < 64) {
        float v0 = -INFINITY, v1 = -INFINITY;
        int i0 = 0, i1 = 0;
        for (int e = 0; e < NEXP; e++) {
            float v = ls[tid][e];
            if (v > v0) { v1 = v0; i1 = i0; v0 = v; i0 = e; }
            else if (v > v1) { v1 = v; i1 = e; }
        }
        // softmax over [v0, v1], v0 >= v1
        float e1 = expf(v1 - v0);
        float p0 = 1.f / (1.f + e1);
        int t = tok0 + tid;
        idx[t * 2 + 0]  = i0;
        idx[t * 2 + 1]  = i1;
        prob[t * 2 + 0] = p0;
        prob[t * 2 + 1] = 1.f - p0;
    }
}

// ---------------------------------------------------------------------------
// Up bilinear + GELU.  Per token: X[32,32], per expert A[64,32], B[64,32]:
//   T = A @ X  (64x32), Y = T @ B^T (64x64), out = gelu(scale * sum_k p_k Y_k + bias)
// One CTA per token, 256 threads.
// ---------------------------------------------------------------------------
__global__ void __launch_bounds__(256, 2)
up_kernel(const float* __restrict__ x,
          const float* __restrict__ A, const float* __restrict__ B,
          const float* __restrict__ scale, const float* __restrict__ bias,
          const int* __restrict__ idx, const float* __restrict__ prob,
          float* __restrict__ h)
{
    __shared__ float Xs[32][33];
    __shared__ float As[64][33];
    __shared__ float Bs[64][33];
    __shared__ float Ts[64][33];

    const int tid = threadIdx.x;
    const int t   = blockIdx.x;

#pragma unroll
    for (int l = tid; l < 1024; l += 256)
        Xs[l >> 5][l & 31] = x[t * 1024 + l];

    float acc[4][4];
#pragma unroll
    for (int i = 0; i < 4; i++)
#pragma unroll
        for (int j = 0; j < 4; j++) acc[i][j] = 0.f;

    // T-stage tile: o in {2*ob, 2*ob+1}, j in 4*jb..+4
    const int ob = tid >> 3;   // 0..31
    const int jb = tid & 7;    // 0..7
    // Y-stage tile: 4x4
    const int yo = (tid >> 4) * 4;  // 0..60
    const int yp = (tid & 15) * 4;  // 0..60

#pragma unroll 1
    for (int k = 0; k < 2; k++) {
        const int   e  = idx[t * 2 + k];
        const float pk = prob[t * 2 + k];
        const float* Ae = A + e * 2048;
        const float* Be = B + e * 2048;
        __syncthreads();   // previous Y-stage done with As/Bs/Ts (also covers Xs on k=0)
#pragma unroll
        for (int l = tid; l < 2048; l += 256) {
            As[l >> 5][l & 31] = Ae[l];
            Bs[l >> 5][l & 31] = Be[l];
        }
        __syncthreads();

        // T = A @ X
        float tacc[2][4];
#pragma unroll
        for (int i = 0; i < 2; i++)
#pragma unroll
            for (int jj = 0; jj < 4; jj++) tacc[i][jj] = 0.f;
#pragma unroll
        for (int i = 0; i < 32; i++) {
            float a0 = As[2 * ob + 0][i];
            float a1 = As[2 * ob + 1][i];
#pragma unroll
            for (int jj = 0; jj < 4; jj++) {
                float xv = Xs[i][4 * jb + jj];
                tacc[0][jj] += a0 * xv;
                tacc[1][jj] += a1 * xv;
            }
        }
#pragma unroll
        for (int i = 0; i < 2; i++)
#pragma unroll
            for (int jj = 0; jj < 4; jj++)
                Ts[2 * ob + i][4 * jb + jj] = tacc[i][jj];
        __syncthreads();

        // Y = T @ B^T
        float yacc[4][4];
#pragma unroll
        for (int i = 0; i < 4; i++)
#pragma unroll
            for (int j = 0; j < 4; j++) yacc[i][j] = 0.f;
#pragma unroll
        for (int j = 0; j < 32; j++) {
            float tv[4], bv[4];
#pragma unroll
            for (int i = 0; i < 4; i++) tv[i] = Ts[yo + i][j];
#pragma unroll
            for (int i = 0; i < 4; i++) bv[i] = Bs[yp + i][j];
#pragma unroll
            for (int i = 0; i < 4; i++)
#pragma unroll
                for (int jj = 0; jj < 4; jj++)
                    yacc[i][jj] += tv[i] * bv[jj];
        }
#pragma unroll
        for (int i = 0; i < 4; i++)
#pragma unroll
            for (int jj = 0; jj < 4; jj++)
                acc[i][jj] += pk * yacc[i][jj];
    }

    const float s = scale[0];
#pragma unroll
    for (int i = 0; i < 4; i++)
#pragma unroll
        for (int jj = 0; jj < 4; jj++) {
            int o = yo + i, p = yp + jj;
            float y = acc[i][jj] * s + bias[o * 64 + p];
            float g = 0.5f * y * (1.f + erff(y * 0.70710678118654752f));
            h[t * 4096 + o * 64 + p] = g;
        }
}

// ---------------------------------------------------------------------------
// Down bilinear + scale/bias. Per token: X[64,64], A[32,64], B[32,64]:
//   T = A @ X (32x64), Y = T @ B^T (32x32)
// ---------------------------------------------------------------------------
__global__ void __launch_bounds__(256, 2)
down_kernel(const float* __restrict__ hbuf,
            const float* __restrict__ A, const float* __restrict__ B,
            const float* __restrict__ scale, const float* __restrict__ bias,
            const int* __restrict__ idx, const float* __restrict__ prob,
            float* __restrict__ out)
{
    __shared__ float Xs[64][65];
    __shared__ float As[32][65];
    __shared__ float Bs[32][65];
    __shared__ float Ts[32][65];

    const int tid = threadIdx.x;
    const int t   = blockIdx.x;

#pragma unroll
    for (int l = tid; l < 4096; l += 256)
        Xs[l >> 6][l & 63] = hbuf[t * 4096 + l];

    float acc[2][2];
    acc[0][0] = acc[0][1] = acc[1][0] = acc[1][1] = 0.f;

    // T-stage: o in {2*ob, 2*ob+1} (ob 0..15), j in 4*jb..+4 (jb 0..15)
    const int ob = tid >> 4;
    const int jb = tid & 15;
    // Y-stage: 2x2 tile: o = 2*ob.., p = 2*jb..

#pragma unroll 1
    for (int k = 0; k < 2; k++) {
        const int   e  = idx[t * 2 + k];
        const float pk = prob[t * 2 + k];
        const float* Ae = A + e * 2048;
        const float* Be = B + e * 2048;
        __syncthreads();
#pragma unroll
        for (int l = tid; l < 2048; l += 256) {
            As[l >> 6][l & 63] = Ae[l];
            Bs[l >> 6][l & 63] = Be[l];
        }
        __syncthreads();

        // T = A @ X
        float tacc[2][4];
#pragma unroll
        for (int i = 0; i < 2; i++)
#pragma unroll
            for (int jj = 0; jj < 4; jj++) tacc[i][jj] = 0.f;
#pragma unroll
        for (int i = 0; i < 64; i++) {
            float a0 = As[2 * ob + 0][i];
            float a1 = As[2 * ob + 1][i];
#pragma unroll
            for (int jj = 0; jj < 4; jj++) {
                float xv = Xs[i][4 * jb + jj];
                tacc[0][jj] += a0 * xv;
                tacc[1][jj] += a1 * xv;
            }
        }
#pragma unroll
        for (int i = 0; i < 2; i++)
#pragma unroll
            for (int jj = 0; jj < 4; jj++)
                Ts[2 * ob + i][4 * jb + jj] = tacc[i][jj];
        __syncthreads();

        // Y = T @ B^T (32x32), 2x2 tile per thread
        float yacc[2][2];
        yacc[0][0] = yacc[0][1] = yacc[1][0] = yacc[1][1] = 0.f;
#pragma unroll
        for (int j = 0; j < 64; j++) {
            float t0 = Ts[2 * ob + 0][j];
            float t1 = Ts[2 * ob + 1][j];
            float b0 = Bs[2 * jb + 0][j];
            float b1 = Bs[2 * jb + 1][j];
            yacc[0][0] += t0 * b0;
            yacc[0][1] += t0 * b1;
            yacc[1][0] += t1 * b0;
            yacc[1][1] += t1 * b1;
        }
        acc[0][0] += pk * yacc[0][0];
        acc[0][1] += pk * yacc[0][1];
        acc[1][0] += pk * yacc[1][0];
        acc[1][1] += pk * yacc[1][1];
    }

    const float s = scale[0];
#pragma unroll
    for (int i = 0; i < 2; i++)
#pragma unroll
        for (int jj = 0; jj < 2; jj++) {
            int o = 2 * ob + i, p = 2 * jb + jj;
            out[t * 1024 + o * 32 + p] = acc[i][jj] * s + bias[o * 32 + p];
        }
}

// ---------------------------------------------------------------------------
extern "C" void kernel_launch(void* const* d_in, const int* in_sizes, int n_in,
                              void* d_out, int out_size)
{
    const float* x          = (const float*)d_in[0];
    const float* W_up       = (const float*)d_in[1];
    const float* A_up       = (const float*)d_in[2];
    const float* B_up       = (const float*)d_in[3];
    const float* scale_up   = (const float*)d_in[4];
    const float* bias_up    = (const float*)d_in[5];
    const float* W_down     = (const float*)d_in[6];
    const float* A_down     = (const float*)d_in[7];
    const float* B_down     = (const float*)d_in[8];
    const float* scale_down = (const float*)d_in[9];
    const float* bias_down  = (const float*)d_in[10];
    float* out = (float*)d_out;

    float *h, *pu, *pd;
    int *iu, *idn;
    cudaGetSymbolAddress((void**)&h,   g_h);
    cudaGetSymbolAddress((void**)&iu,  g_idx_up);
    cudaGetSymbolAddress((void**)&pu,  g_prob_up);
    cudaGetSymbolAddress((void**)&idn, g_idx_dn);
    cudaGetSymbolAddress((void**)&pd,  g_prob_dn);

    router_kernel<1024><<<NTOK / 64, 256>>>(x, W_up, iu, pu);
    up_kernel<<<NTOK, 256>>>(x, A_up, B_up, scale_up, bias_up, iu, pu, h);
    router_kernel<4096><<<NTOK / 64, 256>>>(h, W_down, idn, pd);
    down_kernel<<<NTOK, 256>>>(h, A_down, B_down, scale_down, bias_down, idn, pd, out);
}

// round 2
// speedup vs baseline: 1.0973x; 1.0973x over previous
#include <cuda_runtime.h>
#include <math.h>

#define NTOK 8192
#define NEXP 64

typedef unsigned long long u64;

// Scratch (device globals: allocation-free)
__device__ float g_h[NTOK * 4096];     // up output after GELU (128 MB)
__device__ int   g_idx_up[NTOK * 2];
__device__ float g_prob_up[NTOK * 2];
__device__ int   g_idx_dn[NTOK * 2];
__device__ float g_prob_dn[NTOK * 2];

// packed f32x2 fused multiply-add: d += a * b (two lanes)
__device__ __forceinline__ void ffma2(u64& d, u64 a, u64 b) {
    asm("fma.rn.f32x2 %0, %1, %2, %0;" : "+l"(d) : "l"(a), "l"(b));
}
__device__ __forceinline__ float hadd(u64 a) {
    float lo, hi;
    asm("mov.b64 {%0,%1}, %2;" : "=f"(lo), "=f"(hi) : "l"(a));
    return lo + hi;
}

// ---------------------------------------------------------------------------
// Router: logits = x @ W^T (W: [64, D]) fused top-2 + softmax.
// 64 tokens x 64 experts per CTA, 256 threads, 4x4 tile, K packed in f32x2.
// ---------------------------------------------------------------------------
template <int D>
__global__ void __launch_bounds__(256, 2)
router_kernel(const float* __restrict__ x, const float* __restrict__ W,
              int* __restrict__ idx, float* __restrict__ prob)
{
    __shared__ float xs[64][36];
    __shared__ float ws[64][36];
    __shared__ float ls[64][65];

    const int tid  = threadIdx.x;
    const int tok0 = blockIdx.x * 64;
    const int tr   = (tid >> 4) * 4;   // 4 consecutive token rows
    const int eb   = tid & 15;         // experts eb + 16*j

    u64 acc[4][4];
#pragma unroll
    for (int i = 0; i < 4; i++)
#pragma unroll
        for (int j = 0; j < 4; j++) acc[i][j] = 0ull;

    for (int d0 = 0; d0 < D; d0 += 32) {
        {
            int l = tid;
            int r = l >> 3, c4 = (l & 7) * 4;
            *(float4*)&xs[r][c4] = *(const float4*)&x[(tok0 + r) * D + d0 + c4];
            *(float4*)&ws[r][c4] = *(const float4*)&W[r * D + d0 + c4];
            l += 256;
            r = l >> 3; c4 = (l & 7) * 4;
            *(float4*)&xs[r][c4] = *(const float4*)&x[(tok0 + r) * D + d0 + c4];
            *(float4*)&ws[r][c4] = *(const float4*)&W[r * D + d0 + c4];
        }
        __syncthreads();
#pragma unroll
        for (int d4 = 0; d4 < 32; d4 += 4) {
            ulonglong2 xa[4], wb[4];
#pragma unroll
            for (int i = 0; i < 4; i++)
                xa[i] = *(const ulonglong2*)&xs[tr + i][d4];
#pragma unroll
            for (int j = 0; j < 4; j++)
                wb[j] = *(const ulonglong2*)&ws[eb + 16 * j][d4];
#pragma unroll
            for (int i = 0; i < 4; i++)
#pragma unroll
                for (int j = 0; j < 4; j++) {
                    ffma2(acc[i][j], xa[i].x, wb[j].x);
                    ffma2(acc[i][j], xa[i].y, wb[j].y);
                }
        }
        __syncthreads();
    }

#pragma unroll
    for (int i = 0; i < 4; i++)
#pragma unroll
        for (int j = 0; j < 4; j++)
            ls[tr + i][eb + 16 * j] = hadd(acc[i][j]);
    __syncthreads();

    if (tid < 64) {
        float v0 = -INFINITY, v1 = -INFINITY;
        int i0 = 0, i1 = 0;
        for (int e = 0; e < NEXP; e++) {
            float v = ls[tid][e];
            if (v > v0) { v1 = v0; i1 = i0; v0 = v; i0 = e; }
            else if (v > v1) { v1 = v; i1 = e; }
        }
        float e1 = expf(v1 - v0);
        float p0 = 1.f / (1.f + e1);
        int t = tok0 + tid;
        idx[t * 2 + 0]  = i0;
        idx[t * 2 + 1]  = i1;
        prob[t * 2 + 0] = p0;
        prob[t * 2 + 1] = 1.f - p0;
    }
}

// ---------------------------------------------------------------------------
// Up bilinear + GELU. X[32,32], A[64,32], B[64,32].
//   T = pk * (A @ X)  (64x32), Y += T @ B^T (64x64), gelu(scale*Y + bias)
// K dims packed f32x2; X stored transposed so both stages read K-contiguous.
// ---------------------------------------------------------------------------
__global__ void __launch_bounds__(256, 2)
up_kernel(const float* __restrict__ x,
          const float* __restrict__ A, const float* __restrict__ B,
          const float* __restrict__ scale, const float* __restrict__ bias,
          const int* __restrict__ idx, const float* __restrict__ prob,
          float* __restrict__ h)
{
    __shared__ float XsT[32][36];   // [j][i]
    __shared__ float As[64][36];    // [o][i]
    __shared__ float Bs[64][36];    // [p][j]
    __shared__ float Ts[64][36];    // [o][j]

    const int tid = threadIdx.x;
    const int t   = blockIdx.x;

    // transpose-load X: one float4 per thread
    {
        int i = tid >> 3, j4 = (tid & 7) * 4;
        float4 v = *(const float4*)&x[t * 1024 + i * 32 + j4];
        XsT[j4 + 0][i] = v.x; XsT[j4 + 1][i] = v.y;
        XsT[j4 + 2][i] = v.z; XsT[j4 + 3][i] = v.w;
    }

    const int ob = tid >> 3;          // T: o = 2ob+{0,1}
    const int jb = tid & 7;           // T: j = jb + 8k
    const int yo = (tid >> 4) * 4;    // Y: o rows yo..yo+3
    const int pb = tid & 15;          // Y: p = pb + 16k

    u64 yacc[4][4];
#pragma unroll
    for (int r = 0; r < 4; r++)
#pragma unroll
        for (int k = 0; k < 4; k++) yacc[r][k] = 0ull;

#pragma unroll 1
    for (int kx = 0; kx < 2; kx++) {
        const int   e  = idx[t * 2 + kx];
        const float pk = prob[t * 2 + kx];
        const float* Ae = A + e * 2048;
        const float* Be = B + e * 2048;
        __syncthreads();   // prior stage done with As/Bs/Ts (covers XsT on kx=0)
        {
            int l = tid;
            int r = l >> 3, c4 = (l & 7) * 4;
            *(float4*)&As[r][c4] = *(const float4*)&Ae[r * 32 + c4];
            *(float4*)&Bs[r][c4] = *(const float4*)&Be[r * 32 + c4];
            l += 256;
            r = l >> 3; c4 = (l & 7) * 4;
            *(float4*)&As[r][c4] = *(const float4*)&Ae[r * 32 + c4];
            *(float4*)&Bs[r][c4] = *(const float4*)&Be[r * 32 + c4];
        }
        __syncthreads();

        // T-stage: T[2ob+r][jb+8k] = pk * sum_i A[2ob+r][i] * XsT[jb+8k][i]
        u64 tacc[2][4];
#pragma unroll
        for (int r = 0; r < 2; r++)
#pragma unroll
            for (int k = 0; k < 4; k++) tacc[r][k] = 0ull;
#pragma unroll
        for (int i4 = 0; i4 < 32; i4 += 4) {
            ulonglong2 a0 = *(const ulonglong2*)&As[2 * ob + 0][i4];
            ulonglong2 a1 = *(const ulonglong2*)&As[2 * ob + 1][i4];
#pragma unroll
            for (int k = 0; k < 4; k++) {
                ulonglong2 xv = *(const ulonglong2*)&XsT[jb + 8 * k][i4];
                ffma2(tacc[0][k], a0.x, xv.x);
                ffma2(tacc[0][k], a0.y, xv.y);
                ffma2(tacc[1][k], a1.x, xv.x);
                ffma2(tacc[1][k], a1.y, xv.y);
            }
        }
#pragma unroll
        for (int r = 0; r < 2; r++)
#pragma unroll
            for (int k = 0; k < 4; k++)
                Ts[2 * ob + r][jb + 8 * k] = pk * hadd(tacc[r][k]);
        __syncthreads();

        // Y-stage: yacc[r][k] += sum_j Ts[yo+r][j] * Bs[pb+16k][j]
#pragma unroll
        for (int j4 = 0; j4 < 32; j4 += 4) {
            ulonglong2 tv[4], bv[4];
#pragma unroll
            for (int r = 0; r < 4; r++)
                tv[r] = *(const ulonglong2*)&Ts[yo + r][j4];
#pragma unroll
            for (int k = 0; k < 4; k++)
                bv[k] = *(const ulonglong2*)&Bs[pb + 16 * k][j4];
#pragma unroll
            for (int r = 0; r < 4; r++)
#pragma unroll
                for (int k = 0; k < 4; k++) {
                    ffma2(yacc[r][k], tv[r].x, bv[k].x);
                    ffma2(yacc[r][k], tv[r].y, bv[k].y);
                }
        }
    }

    const float s = scale[0];
#pragma unroll
    for (int r = 0; r < 4; r++)
#pragma unroll
        for (int k = 0; k < 4; k++) {
            int o = yo + r, p = pb + 16 * k;
            float y = hadd(yacc[r][k]) * s + bias[o * 64 + p];
            float g = 0.5f * y * (1.f + erff(y * 0.70710678118654752f));
            h[t * 4096 + o * 64 + p] = g;
        }
}

// ---------------------------------------------------------------------------
// Down bilinear + scale/bias. X[64,64], A[32,64], B[32,64].
//   T = pk * (A @ X) (32x64), Y += T @ B^T (32x32)
// ---------------------------------------------------------------------------
__global__ void __launch_bounds__(256, 2)
down_kernel(const float* __restrict__ hbuf,
            const float* __restrict__ A, const float* __restrict__ B,
            const float* __restrict__ scale, const float* __restrict__ bias,
            const int* __restrict__ idx, const float* __restrict__ prob,
            float* __restrict__ out)
{
    __shared__ float XsT[64][68];   // [j][i]
    __shared__ float As[32][68];    // [o][i]
    __shared__ float Bs[32][68];    // [p][j]
    __shared__ float Ts[32][68];    // [o][j]

    const int tid = threadIdx.x;
    const int t   = blockIdx.x;

    // transpose-load X (= h row): 4 float4 per thread
#pragma unroll
    for (int l = tid; l < 1024; l += 256) {
        int i = l >> 4, j4 = (l & 15) * 4;
        float4 v = *(const float4*)&hbuf[t * 4096 + i * 64 + j4];
        XsT[j4 + 0][i] = v.x; XsT[j4 + 1][i] = v.y;
        XsT[j4 + 2][i] = v.z; XsT[j4 + 3][i] = v.w;
    }

    const int ob = tid >> 4;       // T: o = 2ob+{0,1}
    const int jb = tid & 15;       // T: j = jb + 16k
    const int pb = tid & 15;       // Y: p = pb + 16r'

    u64 yacc[2][2];
    yacc[0][0] = yacc[0][1] = yacc[1][0] = yacc[1][1] = 0ull;

#pragma unroll 1
    for (int kx = 0; kx < 2; kx++) {
        const int   e  = idx[t * 2 + kx];
        const float pk = prob[t * 2 + kx];
        const float* Ae = A + e * 2048;
        const float* Be = B + e * 2048;
        __syncthreads();
        {
            int l = tid;
            int r = l >> 4, c4 = (l & 15) * 4;
            *(float4*)&As[r][c4] = *(const float4*)&Ae[r * 64 + c4];
            *(float4*)&Bs[r][c4] = *(const float4*)&Be[r * 64 + c4];
            l += 256;
            r = l >> 4; c4 = (l & 15) * 4;
            *(float4*)&As[r][c4] = *(const float4*)&Ae[r * 64 + c4];
            *(float4*)&Bs[r][c4] = *(const float4*)&Be[r * 64 + c4];
        }
        __syncthreads();

        // T-stage: T[2ob+r][jb+16k] = pk * sum_i A[2ob+r][i] * XsT[jb+16k][i]
        u64 tacc[2][4];
#pragma unroll
        for (int r = 0; r < 2; r++)
#pragma unroll
            for (int k = 0; k < 4; k++) tacc[r][k] = 0ull;
#pragma unroll
        for (int i4 = 0; i4 < 64; i4 += 4) {
            ulonglong2 a0 = *(const ulonglong2*)&As[2 * ob + 0][i4];
            ulonglong2 a1 = *(const ulonglong2*)&As[2 * ob + 1][i4];
#pragma unroll
            for (int k = 0; k < 4; k++) {
                ulonglong2 xv = *(const ulonglong2*)&XsT[jb + 16 * k][i4];
                ffma2(tacc[0][k], a0.x, xv.x);
                ffma2(tacc[0][k], a0.y, xv.y);
                ffma2(tacc[1][k], a1.x, xv.x);
                ffma2(tacc[1][k], a1.y, xv.y);
            }
        }
#pragma unroll
        for (int r = 0; r < 2; r++)
#pragma unroll
            for (int k = 0; k < 4; k++)
                Ts[2 * ob + r][jb + 16 * k] = pk * hadd(tacc[r][k]);
        __syncthreads();

        // Y-stage: yacc[r][r'] += sum_j Ts[2ob+r][j] * Bs[pb+16r'][j]
#pragma unroll
        for (int j4 = 0; j4 < 64; j4 += 4) {
            ulonglong2 t0 = *(const ulonglong2*)&Ts[2 * ob + 0][j4];
            ulonglong2 t1 = *(const ulonglong2*)&Ts[2 * ob + 1][j4];
            ulonglong2 b0 = *(const ulonglong2*)&Bs[pb + 0][j4];
            ulonglong2 b1 = *(const ulonglong2*)&Bs[pb + 16][j4];
            ffma2(yacc[0][0], t0.x, b0.x); ffma2(yacc[0][0], t0.y, b0.y);
            ffma2(yacc[0][1], t0.x, b1.x); ffma2(yacc[0][1], t0.y, b1.y);
            ffma2(yacc[1][0], t1.x, b0.x); ffma2(yacc[1][0], t1.y, b0.y);
            ffma2(yacc[1][1], t1.x, b1.x); ffma2(yacc[1][1], t1.y, b1.y);
        }
    }

    const float s = scale[0];
#pragma unroll
    for (int r = 0; r < 2; r++)
#pragma unroll
        for (int rp = 0; rp < 2; rp++) {
            int o = 2 * ob + r, p = pb + 16 * rp;
            out[t * 1024 + o * 32 + p] = hadd(yacc[r][rp]) * s + bias[o * 32 + p];
        }
}

// ---------------------------------------------------------------------------
extern "C" void kernel_launch(void* const* d_in, const int* in_sizes, int n_in,
                              void* d_out, int out_size)
{
    const float* x          = (const float*)d_in[0];
    const float* W_up       = (const float*)d_in[1];
    const float* A_up       = (const float*)d_in[2];
    const float* B_up       = (const float*)d_in[3];
    const float* scale_up   = (const float*)d_in[4];
    const float* bias_up    = (const float*)d_in[5];
    const float* W_down     = (const float*)d_in[6];
    const float* A_down     = (const float*)d_in[7];
    const float* B_down     = (const float*)d_in[8];
    const float* scale_down = (const float*)d_in[9];
    const float* bias_down  = (const float*)d_in[10];
    float* out = (float*)d_out;

    float *h, *pu, *pd;
    int *iu, *idn;
    cudaGetSymbolAddress((void**)&h,   g_h);
    cudaGetSymbolAddress((void**)&iu,  g_idx_up);
    cudaGetSymbolAddress((void**)&pu,  g_prob_up);
    cudaGetSymbolAddress((void**)&idn, g_idx_dn);
    cudaGetSymbolAddress((void**)&pd,  g_prob_dn);

    router_kernel<1024><<<NTOK / 64, 256>>>(x, W_up, iu, pu);
    up_kernel<<<NTOK, 256>>>(x, A_up, B_up, scale_up, bias_up, iu, pu, h);
    router_kernel<4096><<<NTOK / 64, 256>>>(h, W_down, idn, pd);
    down_kernel<<<NTOK, 256>>>(h, A_down, B_down, scale_down, bias_down, idn, pd, out);
}